// round 4
// baseline (speedup 1.0000x reference)
#include <cuda_runtime.h>

#define THREADS 256
#define UNROLL 4

__global__ __launch_bounds__(THREADS, 2) void toy_force_kernel(
    const float* __restrict__ pos,
    const float* __restrict__ W1,   // [8,2]
    const float* __restrict__ b1,   // [8]
    const float* __restrict__ W2,   // [4,8]
    const float* __restrict__ b2,   // [4]
    const float* __restrict__ W3,   // [2,4]
    float* __restrict__ out,
    long long n_vec4)
{
    // ---- weights via vectorized loads (17 x LDG.128, L1 broadcast) ----
    float w1[16];
    {
        const float4* v = reinterpret_cast<const float4*>(W1);
        #pragma unroll
        for (int i = 0; i < 4; i++) {
            float4 t = __ldg(&v[i]);
            w1[4*i+0] = t.x; w1[4*i+1] = t.y; w1[4*i+2] = t.z; w1[4*i+3] = t.w;
        }
    }
    float bb1[8];
    {
        const float4* v = reinterpret_cast<const float4*>(b1);
        #pragma unroll
        for (int i = 0; i < 2; i++) {
            float4 t = __ldg(&v[i]);
            bb1[4*i+0] = t.x; bb1[4*i+1] = t.y; bb1[4*i+2] = t.z; bb1[4*i+3] = t.w;
        }
    }
    float w2[32];
    {
        const float4* v = reinterpret_cast<const float4*>(W2);
        #pragma unroll
        for (int i = 0; i < 8; i++) {
            float4 t = __ldg(&v[i]);
            w2[4*i+0] = t.x; w2[4*i+1] = t.y; w2[4*i+2] = t.z; w2[4*i+3] = t.w;
        }
    }
    float bb2[4];
    {
        float4 t = __ldg(reinterpret_cast<const float4*>(b2));
        bb2[0] = t.x; bb2[1] = t.y; bb2[2] = t.z; bb2[3] = t.w;
    }
    float g2[4];  // column sums of W3 [2,4]
    {
        const float4* v = reinterpret_cast<const float4*>(W3);
        float4 r0 = __ldg(&v[0]);
        float4 r1 = __ldg(&v[1]);
        g2[0] = r0.x + r1.x; g2[1] = r0.y + r1.y;
        g2[2] = r0.z + r1.z; g2[3] = r0.w + r1.w;
    }

    const float4* __restrict__ pin  = reinterpret_cast<const float4*>(pos);
    float4* __restrict__       pout = reinterpret_cast<float4*>(out);

    long long chunk  = (long long)THREADS * UNROLL;           // float4s per block-iter
    long long stride = (long long)gridDim.x * chunk;

    for (long long base = (long long)blockIdx.x * chunk + threadIdx.x;
         base < n_vec4 + (long long)THREADS * (UNROLL - 1); base += stride)
    {
        // ---- front-batch the loads: MLP_p1 = UNROLL ----
        float4 p[UNROLL];
        bool   ok[UNROLL];
        #pragma unroll
        for (int u = 0; u < UNROLL; u++) {
            long long idx = base + (long long)u * THREADS;
            ok[u] = idx < n_vec4;
            if (ok[u]) p[u] = pin[idx];
        }

        #pragma unroll
        for (int u = 0; u < UNROLL; u++) {
            if (!ok[u]) continue;
            float4 o;
            #pragma unroll
            for (int s = 0; s < 2; s++) {
                float px = (s == 0) ? p[u].x : p[u].z;
                float py = (s == 0) ? p[u].y : p[u].w;

                // layer 1 forward: z1 = W1 p + b1; h1 = relu(z1)
                float h1[8];
                #pragma unroll
                for (int i = 0; i < 8; i++) {
                    float z = fmaf(w1[2*i], px, fmaf(w1[2*i+1], py, bb1[i]));
                    h1[i] = fmaxf(z, 0.0f);   // FMNMX -> ALU pipe
                }

                // layer 2 forward (sign only needed) + masked grad gh2
                float gh2[4];
                #pragma unroll
                for (int j = 0; j < 4; j++) {
                    float z = bb2[j];
                    #pragma unroll
                    for (int i = 0; i < 8; i++)
                        z = fmaf(w2[8*j+i], h1[i], z);
                    gh2[j] = (z > 0.0f) ? g2[j] : 0.0f;
                }

                // backward: g1 = W2^T gh2, mask by (h1>0), f = -(W1^T gh1)
                float fx = 0.0f, fy = 0.0f;
                #pragma unroll
                for (int i = 0; i < 8; i++) {
                    float g1 = 0.0f;
                    #pragma unroll
                    for (int j = 0; j < 4; j++)
                        g1 = fmaf(w2[8*j+i], gh2[j], g1);
                    float gh1 = (h1[i] > 0.0f) ? g1 : 0.0f;
                    fx = fmaf(w1[2*i],   gh1, fx);
                    fy = fmaf(w1[2*i+1], gh1, fy);
                }
                if (s == 0) { o.x = -fx; o.y = -fy; }
                else        { o.z = -fx; o.w = -fy; }
            }
            long long idx = base + (long long)u * THREADS;
            pout[idx] = o;
        }
    }
}

extern "C" void kernel_launch(void* const* d_in, const int* in_sizes, int n_in,
                              void* d_out, int out_size)
{
    const float* pos = (const float*)d_in[0];
    const float* W1  = (const float*)d_in[1];
    const float* b1  = (const float*)d_in[2];
    const float* W2  = (const float*)d_in[3];
    const float* b2  = (const float*)d_in[4];
    const float* W3  = (const float*)d_in[5];
    float* out = (float*)d_out;

    long long n_floats = in_sizes[0];     // N*2 = 8388608
    long long n_vec4   = n_floats / 4;    // 2097152

    long long chunk  = (long long)THREADS * UNROLL;   // 1024
    long long blocks = (n_vec4 + chunk - 1) / chunk;  // 2048 for N=4194304
    if (blocks > 1048576) blocks = 1048576;

    toy_force_kernel<<<(unsigned)blocks, THREADS>>>(pos, W1, b1, W2, b2, W3, out, n_vec4);
}